// round 1
// baseline (speedup 1.0000x reference)
#include <cuda_runtime.h>
#include <math.h>

// Problem constants
#define NTOK   2048          // tokens (B*S)
#define HID    2048          // hidden
#define INTER_ 1024          // intermediate
#define NEXP   8             // experts
#define TOPK   2
#define NSLOT  (NTOK * TOPK) // 4096 routed slots

// GEMM tiling
#define BM 128
#define BN 64
#define BK 16

// -------- device scratch (no allocation allowed) --------
__device__ int   g_counts[NEXP];
__device__ int   g_offsets[NEXP];
__device__ int   g_token[NSLOT];
__device__ float g_weight[NSLOT];
__device__ float g_inter[(size_t)NSLOT * INTER_];   // 16 MB fp32

// ---------------- routing: bucket sort slots by expert ----------------
// Detects int64 vs int32 expert_indices at runtime: if stored as int64
// (values 0..7, little-endian), every odd 32-bit word is zero.
__global__ void route_kernel(const int* __restrict__ idxw,
                             const float* __restrict__ wts) {
    __shared__ int cnt[NEXP], off[NEXP], cur[NEXP];
    __shared__ int not64;
    int tid = threadIdx.x;
    if (tid < NEXP) { cnt[tid] = 0; cur[tid] = 0; }
    if (tid == 0) not64 = 0;
    __syncthreads();

    int any = 0;
    for (int i = 2 * tid + 1; i < NSLOT; i += 2 * blockDim.x) any |= idxw[i];
    if (any) atomicOr(&not64, 1);
    __syncthreads();
    const int is64 = !not64;

    for (int s = tid; s < NSLOT; s += blockDim.x) {
        int e = is64 ? idxw[2 * s] : idxw[s];
        atomicAdd(&cnt[e], 1);
    }
    __syncthreads();
    if (tid == 0) {
        int acc = 0;
        for (int e = 0; e < NEXP; e++) {
            off[e] = acc; g_offsets[e] = acc; g_counts[e] = cnt[e];
            acc += cnt[e];
        }
    }
    __syncthreads();
    for (int s = tid; s < NSLOT; s += blockDim.x) {
        int e = is64 ? idxw[2 * s] : idxw[s];
        int p = off[e] + atomicAdd(&cur[e], 1);
        g_token[p]  = s >> 1;   // token id (TOPK = 2)
        g_weight[p] = wts[s];
    }
}

// ---------------- zero output ----------------
__global__ void zero_kernel(float4* __restrict__ out, int n4) {
    int i = blockIdx.x * blockDim.x + threadIdx.x;
    if (i < n4) out[i] = make_float4(0.f, 0.f, 0.f, 0.f);
}

// ---------------- GEMM 1: gate + up fused, SwiGLU epilogue ----------------
// grid: (INTER_/BN, NSLOT/BM, NEXP), block 256
__global__ __launch_bounds__(256)
void gemm_gu_kernel(const float* __restrict__ x,
                    const float* __restrict__ gate,
                    const float* __restrict__ up) {
    const int e    = blockIdx.z;
    const int cnt  = g_counts[e];
    const int m0   = blockIdx.y * BM;
    if (m0 >= cnt) return;
    const int base = g_offsets[e];
    const int n0   = blockIdx.x * BN;

    __shared__ float As[BK][BM];
    __shared__ float Bg[BK][BN];
    __shared__ float Bu[BK][BN];
    __shared__ int   sTok[BM];

    const int tid = threadIdx.x;
    if (tid < BM) {
        int r = base + m0 + tid;
        sTok[tid] = g_token[r < NSLOT ? r : NSLOT - 1];
    }
    __syncthreads();

    const float* gbase = gate + (size_t)e * INTER_ * HID + (size_t)n0 * HID;
    const float* ubase = up   + (size_t)e * INTER_ * HID + (size_t)n0 * HID;

    const int tm = tid >> 4;   // 0..15, m stride 16
    const int tn = tid & 15;   // 0..15, n stride 16

    float acc_g[8][4], acc_u[8][4];
    #pragma unroll
    for (int i = 0; i < 8; i++)
        #pragma unroll
        for (int j = 0; j < 4; j++) { acc_g[i][j] = 0.f; acc_u[i][j] = 0.f; }

    const int browB = tid >> 2;   // 0..63
    const int bkqB  = tid & 3;

    for (int k0 = 0; k0 < HID; k0 += BK) {
        // A tile: 128 rows x 16 k (gathered by token)
        #pragma unroll
        for (int it = 0; it < 2; it++) {
            int fidx = tid + it * 256;
            int row  = fidx >> 2;
            int kq   = fidx & 3;
            float4 v = *reinterpret_cast<const float4*>(
                x + (size_t)sTok[row] * HID + k0 + kq * 4);
            As[kq * 4 + 0][row] = v.x;
            As[kq * 4 + 1][row] = v.y;
            As[kq * 4 + 2][row] = v.z;
            As[kq * 4 + 3][row] = v.w;
        }
        // B tiles: 64 rows x 16 k each
        {
            float4 vg = *reinterpret_cast<const float4*>(
                gbase + (size_t)browB * HID + k0 + bkqB * 4);
            Bg[bkqB * 4 + 0][browB] = vg.x;
            Bg[bkqB * 4 + 1][browB] = vg.y;
            Bg[bkqB * 4 + 2][browB] = vg.z;
            Bg[bkqB * 4 + 3][browB] = vg.w;
            float4 vu = *reinterpret_cast<const float4*>(
                ubase + (size_t)browB * HID + k0 + bkqB * 4);
            Bu[bkqB * 4 + 0][browB] = vu.x;
            Bu[bkqB * 4 + 1][browB] = vu.y;
            Bu[bkqB * 4 + 2][browB] = vu.z;
            Bu[bkqB * 4 + 3][browB] = vu.w;
        }
        __syncthreads();

        #pragma unroll
        for (int k = 0; k < BK; k++) {
            float a[8], bg[4], bu[4];
            #pragma unroll
            for (int i = 0; i < 8; i++) a[i] = As[k][tm + i * 16];
            #pragma unroll
            for (int j = 0; j < 4; j++) {
                bg[j] = Bg[k][tn + j * 16];
                bu[j] = Bu[k][tn + j * 16];
            }
            #pragma unroll
            for (int i = 0; i < 8; i++)
                #pragma unroll
                for (int j = 0; j < 4; j++) {
                    acc_g[i][j] = fmaf(a[i], bg[j], acc_g[i][j]);
                    acc_u[i][j] = fmaf(a[i], bu[j], acc_u[i][j]);
                }
        }
        __syncthreads();
    }

    // Epilogue: silu(g) * u * routing_weight -> inter (sorted order)
    #pragma unroll
    for (int i = 0; i < 8; i++) {
        int m = m0 + tm + i * 16;
        if (m >= cnt) continue;
        int r = base + m;
        float w = g_weight[r];
        #pragma unroll
        for (int j = 0; j < 4; j++) {
            float g = acc_g[i][j];
            float s = g / (1.0f + expf(-g));
            g_inter[(size_t)r * INTER_ + n0 + tn + j * 16] = s * acc_u[i][j] * w;
        }
    }
}

// ---------------- GEMM 2: down proj + atomic scatter ----------------
// grid: (HID/BN, NSLOT/BM, NEXP), block 256
__global__ __launch_bounds__(256)
void gemm_down_kernel(const float* __restrict__ down,
                      float* __restrict__ out) {
    const int e    = blockIdx.z;
    const int cnt  = g_counts[e];
    const int m0   = blockIdx.y * BM;
    if (m0 >= cnt) return;
    const int base = g_offsets[e];
    const int n0   = blockIdx.x * BN;   // over HID

    __shared__ float As[BK][BM];
    __shared__ float Bs[BK][BN];

    const int tid = threadIdx.x;
    const float* bbase = down + ((size_t)e * HID + n0) * INTER_;

    const int tm = tid >> 4;
    const int tn = tid & 15;

    float acc[8][4];
    #pragma unroll
    for (int i = 0; i < 8; i++)
        #pragma unroll
        for (int j = 0; j < 4; j++) acc[i][j] = 0.f;

    const int browB = tid >> 2;
    const int bkqB  = tid & 3;

    for (int k0 = 0; k0 < INTER_; k0 += BK) {
        #pragma unroll
        for (int it = 0; it < 2; it++) {
            int fidx = tid + it * 256;
            int row  = fidx >> 2;
            int kq   = fidx & 3;
            int r    = base + m0 + row;
            if (r > NSLOT - 1) r = NSLOT - 1;
            float4 v = *reinterpret_cast<const float4*>(
                g_inter + (size_t)r * INTER_ + k0 + kq * 4);
            As[kq * 4 + 0][row] = v.x;
            As[kq * 4 + 1][row] = v.y;
            As[kq * 4 + 2][row] = v.z;
            As[kq * 4 + 3][row] = v.w;
        }
        {
            float4 vb = *reinterpret_cast<const float4*>(
                bbase + (size_t)browB * INTER_ + k0 + bkqB * 4);
            Bs[bkqB * 4 + 0][browB] = vb.x;
            Bs[bkqB * 4 + 1][browB] = vb.y;
            Bs[bkqB * 4 + 2][browB] = vb.z;
            Bs[bkqB * 4 + 3][browB] = vb.w;
        }
        __syncthreads();

        #pragma unroll
        for (int k = 0; k < BK; k++) {
            float a[8], b[4];
            #pragma unroll
            for (int i = 0; i < 8; i++) a[i] = As[k][tm + i * 16];
            #pragma unroll
            for (int j = 0; j < 4; j++) b[j] = Bs[k][tn + j * 16];
            #pragma unroll
            for (int i = 0; i < 8; i++)
                #pragma unroll
                for (int j = 0; j < 4; j++)
                    acc[i][j] = fmaf(a[i], b[j], acc[i][j]);
        }
        __syncthreads();
    }

    #pragma unroll
    for (int i = 0; i < 8; i++) {
        int m = m0 + tm + i * 16;
        if (m >= cnt) continue;
        int tok = g_token[base + m];
        #pragma unroll
        for (int j = 0; j < 4; j++)
            atomicAdd(&out[(size_t)tok * HID + n0 + tn + j * 16], acc[i][j]);
    }
}

// ---------------- launch ----------------
extern "C" void kernel_launch(void* const* d_in, const int* in_sizes, int n_in,
                              void* d_out, int out_size) {
    const float* x    = (const float*)d_in[0];
    const int*   idxw = (const int*)d_in[1];     // int32 or int64 words; detected on-device
    const float* wts  = (const float*)d_in[2];
    const float* gate = (const float*)d_in[3];
    const float* up   = (const float*)d_in[4];
    const float* down = (const float*)d_in[5];
    float* out = (float*)d_out;

    int n4 = out_size / 4;
    zero_kernel<<<(n4 + 255) / 256, 256>>>((float4*)out, n4);
    route_kernel<<<1, 256>>>(idxw, wts);
    {
        dim3 grid(INTER_ / BN, NSLOT / BM, NEXP);
        gemm_gu_kernel<<<grid, 256>>>(x, gate, up);
    }
    {
        dim3 grid(HID / BN, NSLOT / BM, NEXP);
        gemm_down_kernel<<<grid, 256>>>(down, out);
    }
}

// round 2
// speedup vs baseline: 1.3146x; 1.3146x over previous
#include <cuda_runtime.h>
#include <math.h>

// Problem constants
#define NTOK   2048
#define HID    2048
#define INTER_ 1024
#define NEXP   8
#define TOPK   2
#define NSLOT  (NTOK * TOPK)

#define BM 128
#define BK 16

// -------- device scratch --------
__device__ int   g_counts[NEXP];
__device__ int   g_offsets[NEXP];
__device__ int   g_token[NSLOT];
__device__ float g_weight[NSLOT];
__device__ float g_inter[(size_t)NSLOT * INTER_];   // 16 MB

// ---------------- routing ----------------
__global__ void route_kernel(const int* __restrict__ idxw,
                             const float* __restrict__ wts) {
    __shared__ int cnt[NEXP], off[NEXP], cur[NEXP];
    __shared__ int not64;
    int tid = threadIdx.x;
    if (tid < NEXP) { cnt[tid] = 0; cur[tid] = 0; }
    if (tid == 0) not64 = 0;
    __syncthreads();

    int any = 0;
    for (int i = 2 * tid + 1; i < NSLOT; i += 2 * blockDim.x) any |= idxw[i];
    if (any) atomicOr(&not64, 1);
    __syncthreads();
    const int is64 = !not64;

    for (int s = tid; s < NSLOT; s += blockDim.x) {
        int e = is64 ? idxw[2 * s] : idxw[s];
        atomicAdd(&cnt[e], 1);
    }
    __syncthreads();
    if (tid == 0) {
        int acc = 0;
        for (int e = 0; e < NEXP; e++) {
            off[e] = acc; g_offsets[e] = acc; g_counts[e] = cnt[e];
            acc += cnt[e];
        }
    }
    __syncthreads();
    for (int s = tid; s < NSLOT; s += blockDim.x) {
        int e = is64 ? idxw[2 * s] : idxw[s];
        int p = off[e] + atomicAdd(&cur[e], 1);
        g_token[p]  = s >> 1;
        g_weight[p] = wts[s];
    }
}

__global__ void zero_kernel(float4* __restrict__ out, int n4) {
    int i = blockIdx.x * blockDim.x + threadIdx.x;
    if (i < n4) out[i] = make_float4(0.f, 0.f, 0.f, 0.f);
}

// ---------------- GEMM 1: gate+up fused, SwiGLU epilogue ----------------
// BM=128, BN=64 (for each of gate/up), BK=16. 256 thr, per-thread 8m x (4g+4u).
// Double-buffered smem, register prefetch.
#define GU_BN 64
__global__ __launch_bounds__(256, 2)
void gemm_gu_kernel(const float* __restrict__ x,
                    const float* __restrict__ gate,
                    const float* __restrict__ up) {
    const int e   = blockIdx.z;
    const int cnt = g_counts[e];
    const int m0  = blockIdx.y * BM;
    if (m0 >= cnt) return;
    const int base = g_offsets[e];
    const int n0   = blockIdx.x * GU_BN;

    __shared__ float As[2][BK][BM];
    __shared__ float Bg[2][BK][GU_BN];
    __shared__ float Bu[2][BK][GU_BN];
    __shared__ int   sTok[BM];

    const int tid = threadIdx.x;
    if (tid < BM) {
        int r = base + m0 + tid;
        sTok[tid] = g_token[r < NSLOT ? r : NSLOT - 1];
    }
    __syncthreads();

    const float* gbase = gate + (size_t)e * INTER_ * HID + (size_t)n0 * HID;
    const float* ubase = up   + (size_t)e * INTER_ * HID + (size_t)n0 * HID;

    // load indices
    const int lrow = tid >> 2;        // 0..63  (A uses lrow and lrow+64)
    const int lkq  = tid & 3;         // k-quad
    const int arow0 = lrow, arow1 = lrow + 64;

    // compute indices
    const int ty = tid >> 4;          // 0..15 -> m = ty*8..+7
    const int tx = tid & 15;          // 0..15 -> n = tx*4..+3

    float acc_g[8][4], acc_u[8][4];
    #pragma unroll
    for (int i = 0; i < 8; i++)
        #pragma unroll
        for (int j = 0; j < 4; j++) { acc_g[i][j] = 0.f; acc_u[i][j] = 0.f; }

    const size_t tokA0 = (size_t)sTok[arow0] * HID;
    const size_t tokA1 = (size_t)sTok[arow1] * HID;

    // prologue: load tile 0
    float4 pa0 = *reinterpret_cast<const float4*>(x + tokA0 + lkq * 4);
    float4 pa1 = *reinterpret_cast<const float4*>(x + tokA1 + lkq * 4);
    float4 pg  = *reinterpret_cast<const float4*>(gbase + (size_t)lrow * HID + lkq * 4);
    float4 pu  = *reinterpret_cast<const float4*>(ubase + (size_t)lrow * HID + lkq * 4);

    int cur = 0;
    {
        As[0][lkq*4+0][arow0]=pa0.x; As[0][lkq*4+1][arow0]=pa0.y; As[0][lkq*4+2][arow0]=pa0.z; As[0][lkq*4+3][arow0]=pa0.w;
        As[0][lkq*4+0][arow1]=pa1.x; As[0][lkq*4+1][arow1]=pa1.y; As[0][lkq*4+2][arow1]=pa1.z; As[0][lkq*4+3][arow1]=pa1.w;
        Bg[0][lkq*4+0][lrow]=pg.x;   Bg[0][lkq*4+1][lrow]=pg.y;   Bg[0][lkq*4+2][lrow]=pg.z;   Bg[0][lkq*4+3][lrow]=pg.w;
        Bu[0][lkq*4+0][lrow]=pu.x;   Bu[0][lkq*4+1][lrow]=pu.y;   Bu[0][lkq*4+2][lrow]=pu.z;   Bu[0][lkq*4+3][lrow]=pu.w;
    }
    __syncthreads();

    const int NITER = HID / BK;
    for (int it = 0; it < NITER; it++) {
        if (it + 1 < NITER) {
            int k0 = (it + 1) * BK;
            pa0 = *reinterpret_cast<const float4*>(x + tokA0 + k0 + lkq * 4);
            pa1 = *reinterpret_cast<const float4*>(x + tokA1 + k0 + lkq * 4);
            pg  = *reinterpret_cast<const float4*>(gbase + (size_t)lrow * HID + k0 + lkq * 4);
            pu  = *reinterpret_cast<const float4*>(ubase + (size_t)lrow * HID + k0 + lkq * 4);
        }
        #pragma unroll
        for (int k = 0; k < BK; k++) {
            float4 a0 = *reinterpret_cast<const float4*>(&As[cur][k][ty * 8]);
            float4 a1 = *reinterpret_cast<const float4*>(&As[cur][k][ty * 8 + 4]);
            float4 bg = *reinterpret_cast<const float4*>(&Bg[cur][k][tx * 4]);
            float4 bu = *reinterpret_cast<const float4*>(&Bu[cur][k][tx * 4]);
            float a[8] = {a0.x,a0.y,a0.z,a0.w,a1.x,a1.y,a1.z,a1.w};
            float g4[4] = {bg.x,bg.y,bg.z,bg.w};
            float u4[4] = {bu.x,bu.y,bu.z,bu.w};
            #pragma unroll
            for (int i = 0; i < 8; i++)
                #pragma unroll
                for (int j = 0; j < 4; j++) {
                    acc_g[i][j] = fmaf(a[i], g4[j], acc_g[i][j]);
                    acc_u[i][j] = fmaf(a[i], u4[j], acc_u[i][j]);
                }
        }
        if (it + 1 < NITER) {
            int nb = cur ^ 1;
            As[nb][lkq*4+0][arow0]=pa0.x; As[nb][lkq*4+1][arow0]=pa0.y; As[nb][lkq*4+2][arow0]=pa0.z; As[nb][lkq*4+3][arow0]=pa0.w;
            As[nb][lkq*4+0][arow1]=pa1.x; As[nb][lkq*4+1][arow1]=pa1.y; As[nb][lkq*4+2][arow1]=pa1.z; As[nb][lkq*4+3][arow1]=pa1.w;
            Bg[nb][lkq*4+0][lrow]=pg.x;   Bg[nb][lkq*4+1][lrow]=pg.y;   Bg[nb][lkq*4+2][lrow]=pg.z;   Bg[nb][lkq*4+3][lrow]=pg.w;
            Bu[nb][lkq*4+0][lrow]=pu.x;   Bu[nb][lkq*4+1][lrow]=pu.y;   Bu[nb][lkq*4+2][lrow]=pu.z;   Bu[nb][lkq*4+3][lrow]=pu.w;
            __syncthreads();
            cur = nb;
        }
    }

    // Epilogue: silu(g)*u*w -> inter (sorted order)
    #pragma unroll
    for (int i = 0; i < 8; i++) {
        int m = m0 + ty * 8 + i;
        if (m >= cnt) continue;
        int r = base + m;
        float w = g_weight[r];
        float4 o;
        float* po = &o.x;
        #pragma unroll
        for (int j = 0; j < 4; j++) {
            float g = acc_g[i][j];
            float s = g / (1.0f + expf(-g));
            po[j] = s * acc_u[i][j] * w;
        }
        *reinterpret_cast<float4*>(&g_inter[(size_t)r * INTER_ + n0 + tx * 4]) = o;
    }
}

// ---------------- GEMM 2: down proj + atomic scatter ----------------
// BM=128, BN=128, BK=16. 256 thr, 8x8 per thread.
#define DN_BN 128
__global__ __launch_bounds__(256, 2)
void gemm_down_kernel(const float* __restrict__ down,
                      float* __restrict__ out) {
    const int e   = blockIdx.z;
    const int cnt = g_counts[e];
    const int m0  = blockIdx.y * BM;
    if (m0 >= cnt) return;
    const int base = g_offsets[e];
    const int n0   = blockIdx.x * DN_BN;

    __shared__ float As[2][BK][BM];
    __shared__ float Bs[2][BK][DN_BN];

    const int tid = threadIdx.x;
    const float* bbase = down + ((size_t)e * HID + n0) * INTER_;

    const int lrow = tid >> 2;
    const int lkq  = tid & 3;
    const int arow0 = lrow, arow1 = lrow + 64;

    const int ty = tid >> 4;
    const int tx = tid & 15;

    float acc[8][8];
    #pragma unroll
    for (int i = 0; i < 8; i++)
        #pragma unroll
        for (int j = 0; j < 8; j++) acc[i][j] = 0.f;

    int rA0 = base + m0 + arow0; if (rA0 > NSLOT - 1) rA0 = NSLOT - 1;
    int rA1 = base + m0 + arow1; if (rA1 > NSLOT - 1) rA1 = NSLOT - 1;
    const float* aptr0 = g_inter + (size_t)rA0 * INTER_;
    const float* aptr1 = g_inter + (size_t)rA1 * INTER_;

    float4 pa0 = *reinterpret_cast<const float4*>(aptr0 + lkq * 4);
    float4 pa1 = *reinterpret_cast<const float4*>(aptr1 + lkq * 4);
    float4 pb0 = *reinterpret_cast<const float4*>(bbase + (size_t)arow0 * INTER_ + lkq * 4);
    float4 pb1 = *reinterpret_cast<const float4*>(bbase + (size_t)arow1 * INTER_ + lkq * 4);

    int cur = 0;
    {
        As[0][lkq*4+0][arow0]=pa0.x; As[0][lkq*4+1][arow0]=pa0.y; As[0][lkq*4+2][arow0]=pa0.z; As[0][lkq*4+3][arow0]=pa0.w;
        As[0][lkq*4+0][arow1]=pa1.x; As[0][lkq*4+1][arow1]=pa1.y; As[0][lkq*4+2][arow1]=pa1.z; As[0][lkq*4+3][arow1]=pa1.w;
        Bs[0][lkq*4+0][arow0]=pb0.x; Bs[0][lkq*4+1][arow0]=pb0.y; Bs[0][lkq*4+2][arow0]=pb0.z; Bs[0][lkq*4+3][arow0]=pb0.w;
        Bs[0][lkq*4+0][arow1]=pb1.x; Bs[0][lkq*4+1][arow1]=pb1.y; Bs[0][lkq*4+2][arow1]=pb1.z; Bs[0][lkq*4+3][arow1]=pb1.w;
    }
    __syncthreads();

    const int NITER = INTER_ / BK;
    for (int it = 0; it < NITER; it++) {
        if (it + 1 < NITER) {
            int k0 = (it + 1) * BK;
            pa0 = *reinterpret_cast<const float4*>(aptr0 + k0 + lkq * 4);
            pa1 = *reinterpret_cast<const float4*>(aptr1 + k0 + lkq * 4);
            pb0 = *reinterpret_cast<const float4*>(bbase + (size_t)arow0 * INTER_ + k0 + lkq * 4);
            pb1 = *reinterpret_cast<const float4*>(bbase + (size_t)arow1 * INTER_ + k0 + lkq * 4);
        }
        #pragma unroll
        for (int k = 0; k < BK; k++) {
            float4 a0 = *reinterpret_cast<const float4*>(&As[cur][k][ty * 8]);
            float4 a1 = *reinterpret_cast<const float4*>(&As[cur][k][ty * 8 + 4]);
            float4 b0 = *reinterpret_cast<const float4*>(&Bs[cur][k][tx * 8]);
            float4 b1 = *reinterpret_cast<const float4*>(&Bs[cur][k][tx * 8 + 4]);
            float a[8] = {a0.x,a0.y,a0.z,a0.w,a1.x,a1.y,a1.z,a1.w};
            float b[8] = {b0.x,b0.y,b0.z,b0.w,b1.x,b1.y,b1.z,b1.w};
            #pragma unroll
            for (int i = 0; i < 8; i++)
                #pragma unroll
                for (int j = 0; j < 8; j++)
                    acc[i][j] = fmaf(a[i], b[j], acc[i][j]);
        }
        if (it + 1 < NITER) {
            int nb = cur ^ 1;
            As[nb][lkq*4+0][arow0]=pa0.x; As[nb][lkq*4+1][arow0]=pa0.y; As[nb][lkq*4+2][arow0]=pa0.z; As[nb][lkq*4+3][arow0]=pa0.w;
            As[nb][lkq*4+0][arow1]=pa1.x; As[nb][lkq*4+1][arow1]=pa1.y; As[nb][lkq*4+2][arow1]=pa1.z; As[nb][lkq*4+3][arow1]=pa1.w;
            Bs[nb][lkq*4+0][arow0]=pb0.x; Bs[nb][lkq*4+1][arow0]=pb0.y; Bs[nb][lkq*4+2][arow0]=pb0.z; Bs[nb][lkq*4+3][arow0]=pb0.w;
            Bs[nb][lkq*4+0][arow1]=pb1.x; Bs[nb][lkq*4+1][arow1]=pb1.y; Bs[nb][lkq*4+2][arow1]=pb1.z; Bs[nb][lkq*4+3][arow1]=pb1.w;
            __syncthreads();
            cur = nb;
        }
    }

    #pragma unroll
    for (int i = 0; i < 8; i++) {
        int m = m0 + ty * 8 + i;
        if (m >= cnt) continue;
        int tok = g_token[base + m];
        float* orow = out + (size_t)tok * HID + n0;
        #pragma unroll
        for (int j = 0; j < 8; j++)
            atomicAdd(&orow[tx * 8 + j], acc[i][j]);
    }
}

// ---------------- launch ----------------
extern "C" void kernel_launch(void* const* d_in, const int* in_sizes, int n_in,
                              void* d_out, int out_size) {
    const float* x    = (const float*)d_in[0];
    const int*   idxw = (const int*)d_in[1];
    const float* wts  = (const float*)d_in[2];
    const float* gate = (const float*)d_in[3];
    const float* up   = (const float*)d_in[4];
    const float* down = (const float*)d_in[5];
    float* out = (float*)d_out;

    int n4 = out_size / 4;
    zero_kernel<<<(n4 + 255) / 256, 256>>>((float4*)out, n4);
    route_kernel<<<1, 256>>>(idxw, wts);
    {
        dim3 grid(INTER_ / GU_BN, NSLOT / BM, NEXP);
        gemm_gu_kernel<<<grid, 256>>>(x, gate, up);
    }
    {
        dim3 grid(HID / DN_BN, NSLOT / BM, NEXP);
        gemm_down_kernel<<<grid, 256>>>(down, out);
    }
}

// round 5
// speedup vs baseline: 1.3217x; 1.0054x over previous
#include <cuda_runtime.h>
#include <math.h>
#include <stdint.h>

// Problem constants
#define NTOK   2048
#define HID    2048
#define INTER_ 1024
#define NEXP   8
#define TOPK   2
#define NSLOT  (NTOK * TOPK)

// MMA tiling: block 128x128, 8 warps (2x4), warp 64x32, k-tile 32
#define KT 32
#define SA 36                       // smem row stride (floats), conflict-free
#define TILE_B (128 * SA * 4)       // 18432 bytes per operand tile

// shared memory layout (bytes)
#define SM_TOK 0
#define SM_W   512
#define SM_BUF 1024
#define SM_A_OFF(b) (SM_BUF + (b) * 2 * TILE_B)
#define SM_B_OFF(b) (SM_BUF + (b) * 2 * TILE_B + TILE_B)
#define SM_TOTAL (SM_BUF + 4 * TILE_B)    // 74752
#define SM_CS 1024
#define CS_STRIDE 132

// -------- device scratch --------
__device__ int   g_counts[NEXP];
__device__ int   g_offsets[NEXP];
__device__ int   g_token[NSLOT];
__device__ float g_weight[NSLOT];
__device__ float g_inter[(size_t)NSLOT * INTER_];

// ---------------- helpers ----------------
__device__ __forceinline__ uint32_t smem_u32(const void* p) {
    uint32_t a;
    asm("{ .reg .u64 t; cvta.to.shared.u64 t, %1; cvt.u32.u64 %0, t; }" : "=r"(a) : "l"(p));
    return a;
}
#define CP16(sm, gm) asm volatile("cp.async.cg.shared.global [%0], [%1], 16;" :: "r"(sm), "l"(gm))
#define CP_COMMIT()  asm volatile("cp.async.commit_group;" ::: "memory")
#define CP_WAIT(n)   asm volatile("cp.async.wait_group %0;" :: "n"(n) : "memory")

__device__ __forceinline__ uint32_t tf32_rna(float x) {
    uint32_t r;
    asm("cvt.rna.tf32.f32 %0, %1;" : "=r"(r) : "f"(x));
    return r;
}
// split v into hi (tf32-rounded) and lo (tf32 of remainder)
__device__ __forceinline__ void tf32_split(float v, uint32_t& hi, uint32_t& lo) {
    hi = tf32_rna(v);
    lo = tf32_rna(v - __uint_as_float(hi));
}

__device__ __forceinline__ void mma_tf32u(float* c, const uint32_t* a, const uint32_t* b) {
    asm volatile(
        "mma.sync.aligned.m16n8k8.row.col.f32.tf32.tf32.f32 "
        "{%0,%1,%2,%3}, {%4,%5,%6,%7}, {%8,%9}, {%0,%1,%2,%3};\n"
        : "+f"(c[0]), "+f"(c[1]), "+f"(c[2]), "+f"(c[3])
        : "r"(a[0]), "r"(a[1]), "r"(a[2]), "r"(a[3]),
          "r"(b[0]), "r"(b[1]));
}

// ---------------- routing ----------------
__global__ void route_kernel(const int* __restrict__ idxw,
                             const float* __restrict__ wts) {
    __shared__ int cnt[NEXP], off[NEXP], cur[NEXP];
    __shared__ int not64;
    int tid = threadIdx.x;
    if (tid < NEXP) { cnt[tid] = 0; cur[tid] = 0; }
    if (tid == 0) not64 = 0;
    __syncthreads();
    int any = 0;
    for (int i = 2 * tid + 1; i < NSLOT; i += 2 * blockDim.x) any |= idxw[i];
    if (any) atomicOr(&not64, 1);
    __syncthreads();
    const int is64 = !not64;
    for (int s = tid; s < NSLOT; s += blockDim.x) {
        int e = is64 ? idxw[2 * s] : idxw[s];
        atomicAdd(&cnt[e], 1);
    }
    __syncthreads();
    if (tid == 0) {
        int acc = 0;
        for (int e = 0; e < NEXP; e++) {
            off[e] = acc; g_offsets[e] = acc; g_counts[e] = cnt[e];
            acc += cnt[e];
        }
    }
    __syncthreads();
    for (int s = tid; s < NSLOT; s += blockDim.x) {
        int e = is64 ? idxw[2 * s] : idxw[s];
        int p = off[e] + atomicAdd(&cur[e], 1);
        g_token[p]  = s >> 1;
        g_weight[p] = wts[s];
    }
}

__global__ void zero_kernel(float4* __restrict__ out, int n4) {
    int i = blockIdx.x * blockDim.x + threadIdx.x;
    if (i < n4) out[i] = make_float4(0.f, 0.f, 0.f, 0.f);
}

// ---------------- GEMM 1: gate+up via 3xTF32 mma ----------------
// grid (INTER_/64=16, 32, NEXP). Tile: M=128 slots, 64 gate cols + 64 up cols.
__global__ __launch_bounds__(256)
void gemm_gu_mma(const float* __restrict__ x,
                 const float* __restrict__ gate,
                 const float* __restrict__ up) {
    const int e   = blockIdx.z;
    const int cnt = g_counts[e];
    const int m0  = blockIdx.y * 128;
    if (m0 >= cnt) return;
    const int base = g_offsets[e];
    const int n0   = blockIdx.x * 64;

    extern __shared__ char smem[];
    const uint32_t sb = smem_u32(smem);
    int*   sTok = (int*)smem;
    float* sW   = (float*)(smem + SM_W);

    const int tid  = threadIdx.x;
    const int wid  = tid >> 5;
    const int lane = tid & 31;

    if (tid < 128) {
        int m = m0 + tid;
        int r = base + (m < cnt ? m : cnt - 1);
        sTok[tid] = g_token[r];
        sW[tid]   = (m < cnt) ? g_weight[r] : 0.f;
    }
    __syncthreads();

    const int lrow  = tid >> 1;
    const int lhalf = tid & 1;
    const float* aRow = x + (size_t)sTok[lrow] * HID + lhalf * 16;
    const float* bRow = (lrow < 64)
        ? gate + (size_t)e * INTER_ * HID + (size_t)(n0 + lrow) * HID + lhalf * 16
        : up   + (size_t)e * INTER_ * HID + (size_t)(n0 + lrow - 64) * HID + lhalf * 16;
    const uint32_t rowoff = (uint32_t)(lrow * SA * 4 + lhalf * 64);

    const int wm = wid >> 2, wn = wid & 3;
    const int g  = lane >> 2, t4 = lane & 3;

    float acc[4][4][4];
    #pragma unroll
    for (int i = 0; i < 4; i++)
        #pragma unroll
        for (int j = 0; j < 4; j++)
            #pragma unroll
            for (int r = 0; r < 4; r++) acc[i][j][r] = 0.f;

    const int NT = HID / KT;   // 64

    {
        uint32_t dA = sb + SM_A_OFF(0) + rowoff;
        uint32_t dB = sb + SM_B_OFF(0) + rowoff;
        #pragma unroll
        for (int q = 0; q < 4; q++) {
            CP16(dA + q * 16, aRow + q * 4);
            CP16(dB + q * 16, bRow + q * 4);
        }
        CP_COMMIT();
    }

    for (int t = 0; t < NT; t++) {
        if (t + 1 < NT) {
            int k0 = (t + 1) * KT;
            uint32_t dA = sb + SM_A_OFF((t + 1) & 1) + rowoff;
            uint32_t dB = sb + SM_B_OFF((t + 1) & 1) + rowoff;
            #pragma unroll
            for (int q = 0; q < 4; q++) {
                CP16(dA + q * 16, aRow + k0 + q * 4);
                CP16(dB + q * 16, bRow + k0 + q * 4);
            }
            CP_COMMIT();
            CP_WAIT(1);
        } else {
            CP_WAIT(0);
        }
        __syncthreads();

        const float* As = (const float*)(smem + SM_A_OFF(t & 1));
        const float* Bs = (const float*)(smem + SM_B_OFF(t & 1));
        #pragma unroll
        for (int ks = 0; ks < 4; ks++) {
            const int kb = ks * 8 + t4;
            uint32_t ah[4][4], al[4][4];
            #pragma unroll
            for (int mt = 0; mt < 4; mt++) {
                int r = wm * 64 + mt * 16 + g;
                tf32_split(As[r * SA + kb],           ah[mt][0], al[mt][0]);
                tf32_split(As[(r + 8) * SA + kb],     ah[mt][1], al[mt][1]);
                tf32_split(As[r * SA + kb + 4],       ah[mt][2], al[mt][2]);
                tf32_split(As[(r + 8) * SA + kb + 4], ah[mt][3], al[mt][3]);
            }
            uint32_t bh[4][2], bl[4][2];
            #pragma unroll
            for (int nt = 0; nt < 4; nt++) {
                int rn = wn * 32 + nt * 8 + g;
                tf32_split(Bs[rn * SA + kb],     bh[nt][0], bl[nt][0]);
                tf32_split(Bs[rn * SA + kb + 4], bh[nt][1], bl[nt][1]);
            }
            #pragma unroll
            for (int mt = 0; mt < 4; mt++)
                #pragma unroll
                for (int nt = 0; nt < 4; nt++) {
                    mma_tf32u(acc[mt][nt], al[mt], bh[nt]);
                    mma_tf32u(acc[mt][nt], ah[mt], bl[nt]);
                    mma_tf32u(acc[mt][nt], ah[mt], bh[nt]);
                }
        }
        __syncthreads();
    }

    // stage accumulators to smem, then SwiGLU-combine
    float* Cs = (float*)(smem + SM_CS);
    #pragma unroll
    for (int mt = 0; mt < 4; mt++) {
        #pragma unroll
        for (int nt = 0; nt < 4; nt++) {
            int row = wm * 64 + mt * 16 + g;
            int col = wn * 32 + nt * 8 + t4 * 2;
            *reinterpret_cast<float2*>(&Cs[row * CS_STRIDE + col]) =
                make_float2(acc[mt][nt][0], acc[mt][nt][1]);
            *reinterpret_cast<float2*>(&Cs[(row + 8) * CS_STRIDE + col]) =
                make_float2(acc[mt][nt][2], acc[mt][nt][3]);
        }
    }
    __syncthreads();

    const int jj = (tid & 15) * 4;
    const int rb = (tid >> 4) * 8;
    #pragma unroll
    for (int mm = 0; mm < 8; mm++) {
        int m = rb + mm;
        if (m0 + m >= cnt) continue;
        float w = sW[m];
        float4 gv = *reinterpret_cast<const float4*>(&Cs[m * CS_STRIDE + jj]);
        float4 uv = *reinterpret_cast<const float4*>(&Cs[m * CS_STRIDE + 64 + jj]);
        float4 o;
        o.x = (gv.x / (1.f + __expf(-gv.x))) * uv.x * w;
        o.y = (gv.y / (1.f + __expf(-gv.y))) * uv.y * w;
        o.z = (gv.z / (1.f + __expf(-gv.z))) * uv.z * w;
        o.w = (gv.w / (1.f + __expf(-gv.w))) * uv.w * w;
        *reinterpret_cast<float4*>(
            &g_inter[(size_t)(base + m0 + m) * INTER_ + n0 + jj]) = o;
    }
}

// ---------------- GEMM 2: down via 3xTF32 mma + scatter ----------------
// grid (HID/128=16, 32, NEXP). Tile 128x128.
__global__ __launch_bounds__(256)
void gemm_down_mma(const float* __restrict__ down,
                   float* __restrict__ out) {
    const int e   = blockIdx.z;
    const int cnt = g_counts[e];
    const int m0  = blockIdx.y * 128;
    if (m0 >= cnt) return;
    const int base = g_offsets[e];
    const int n0   = blockIdx.x * 128;

    extern __shared__ char smem[];
    const uint32_t sb = smem_u32(smem);
    int* sTok = (int*)smem;

    const int tid  = threadIdx.x;
    const int wid  = tid >> 5;
    const int lane = tid & 31;

    if (tid < 128) {
        int m = m0 + tid;
        int r = base + (m < cnt ? m : cnt - 1);
        sTok[tid] = g_token[r];
    }
    __syncthreads();

    const int lrow  = tid >> 1;
    const int lhalf = tid & 1;
    int ar = base + m0 + lrow; if (ar > NSLOT - 1) ar = NSLOT - 1;
    const float* aRow = g_inter + (size_t)ar * INTER_ + lhalf * 16;
    const float* bRow = down + ((size_t)e * HID + n0 + lrow) * INTER_ + lhalf * 16;
    const uint32_t rowoff = (uint32_t)(lrow * SA * 4 + lhalf * 64);

    const int wm = wid >> 2, wn = wid & 3;
    const int g  = lane >> 2, t4 = lane & 3;

    float acc[4][4][4];
    #pragma unroll
    for (int i = 0; i < 4; i++)
        #pragma unroll
        for (int j = 0; j < 4; j++)
            #pragma unroll
            for (int r = 0; r < 4; r++) acc[i][j][r] = 0.f;

    const int NT = INTER_ / KT;   // 32

    {
        uint32_t dA = sb + SM_A_OFF(0) + rowoff;
        uint32_t dB = sb + SM_B_OFF(0) + rowoff;
        #pragma unroll
        for (int q = 0; q < 4; q++) {
            CP16(dA + q * 16, aRow + q * 4);
            CP16(dB + q * 16, bRow + q * 4);
        }
        CP_COMMIT();
    }

    for (int t = 0; t < NT; t++) {
        if (t + 1 < NT) {
            int k0 = (t + 1) * KT;
            uint32_t dA = sb + SM_A_OFF((t + 1) & 1) + rowoff;
            uint32_t dB = sb + SM_B_OFF((t + 1) & 1) + rowoff;
            #pragma unroll
            for (int q = 0; q < 4; q++) {
                CP16(dA + q * 16, aRow + k0 + q * 4);
                CP16(dB + q * 16, bRow + k0 + q * 4);
            }
            CP_COMMIT();
            CP_WAIT(1);
        } else {
            CP_WAIT(0);
        }
        __syncthreads();

        const float* As = (const float*)(smem + SM_A_OFF(t & 1));
        const float* Bs = (const float*)(smem + SM_B_OFF(t & 1));
        #pragma unroll
        for (int ks = 0; ks < 4; ks++) {
            const int kb = ks * 8 + t4;
            uint32_t ah[4][4], al[4][4];
            #pragma unroll
            for (int mt = 0; mt < 4; mt++) {
                int r = wm * 64 + mt * 16 + g;
                tf32_split(As[r * SA + kb],           ah[mt][0], al[mt][0]);
                tf32_split(As[(r + 8) * SA + kb],     ah[mt][1], al[mt][1]);
                tf32_split(As[r * SA + kb + 4],       ah[mt][2], al[mt][2]);
                tf32_split(As[(r + 8) * SA + kb + 4], ah[mt][3], al[mt][3]);
            }
            uint32_t bh[4][2], bl[4][2];
            #pragma unroll
            for (int nt = 0; nt < 4; nt++) {
                int rn = wn * 32 + nt * 8 + g;
                tf32_split(Bs[rn * SA + kb],     bh[nt][0], bl[nt][0]);
                tf32_split(Bs[rn * SA + kb + 4], bh[nt][1], bl[nt][1]);
            }
            #pragma unroll
            for (int mt = 0; mt < 4; mt++)
                #pragma unroll
                for (int nt = 0; nt < 4; nt++) {
                    mma_tf32u(acc[mt][nt], al[mt], bh[nt]);
                    mma_tf32u(acc[mt][nt], ah[mt], bl[nt]);
                    mma_tf32u(acc[mt][nt], ah[mt], bh[nt]);
                }
        }
        __syncthreads();
    }

    // scatter: atomicAdd fragments into out rows by token
    #pragma unroll
    for (int mt = 0; mt < 4; mt++) {
        int row0 = wm * 64 + mt * 16 + g;
        int row1 = row0 + 8;
        bool v0 = (m0 + row0 < cnt);
        bool v1 = (m0 + row1 < cnt);
        float* o0 = out + (size_t)sTok[row0] * HID + n0;
        float* o1 = out + (size_t)sTok[row1] * HID + n0;
        #pragma unroll
        for (int nt = 0; nt < 4; nt++) {
            int col = wn * 32 + nt * 8 + t4 * 2;
            if (v0) {
                atomicAdd(&o0[col],     acc[mt][nt][0]);
                atomicAdd(&o0[col + 1], acc[mt][nt][1]);
            }
            if (v1) {
                atomicAdd(&o1[col],     acc[mt][nt][2]);
                atomicAdd(&o1[col + 1], acc[mt][nt][3]);
            }
        }
    }
}

// ---------------- launch ----------------
extern "C" void kernel_launch(void* const* d_in, const int* in_sizes, int n_in,
                              void* d_out, int out_size) {
    const float* x    = (const float*)d_in[0];
    const int*   idxw = (const int*)d_in[1];
    const float* wts  = (const float*)d_in[2];
    const float* gate = (const float*)d_in[3];
    const float* up   = (const float*)d_in[4];
    const float* down = (const float*)d_in[5];
    float* out = (float*)d_out;

    cudaFuncSetAttribute(gemm_gu_mma,   cudaFuncAttributeMaxDynamicSharedMemorySize, SM_TOTAL);
    cudaFuncSetAttribute(gemm_down_mma, cudaFuncAttributeMaxDynamicSharedMemorySize, SM_TOTAL);

    int n4 = out_size / 4;
    zero_kernel<<<(n4 + 255) / 256, 256>>>((float4*)out, n4);
    route_kernel<<<1, 256>>>(idxw, wts);
    {
        dim3 grid(INTER_ / 64, NSLOT / 128, NEXP);
        gemm_gu_mma<<<grid, 256, SM_TOTAL>>>(x, gate, up);
    }
    {
        dim3 grid(HID / 128, NSLOT / 128, NEXP);
        gemm_down_mma<<<grid, 256, SM_TOTAL>>>(down, out);
    }
}

// round 6
// speedup vs baseline: 2.4600x; 1.8613x over previous
#include <cuda_runtime.h>
#include <cuda_bf16.h>
#include <math.h>
#include <stdint.h>

// Problem constants
#define NTOK   2048
#define HID    2048
#define INTER_ 1024
#define NEXP   8
#define TOPK   2
#define NSLOT  (NTOK * TOPK)

// MMA tiling: block 128x128 C, 8 warps (2x4), warp 64x32, k-tile 32 (bf16 halves)
#define KT    32
#define ROWB  80          // bytes per padded smem row (64B data + 16B pad)
#define ROWW  20          // 32-bit words per row
#define TILE  10240       // 128 rows * 80B
#define SM_BUF 1024
#define SM_AH(b) (SM_BUF + (b) * 4 * TILE)
#define SM_AL(b) (SM_AH(b) + TILE)
#define SM_BH(b) (SM_AH(b) + 2 * TILE)
#define SM_BL(b) (SM_AH(b) + 3 * TILE)
#define SM_TOTAL (SM_BUF + 8 * TILE)     // 82944
#define CS_STRIDE 132

// -------- device scratch --------
__device__ int   g_counts[NEXP];
__device__ int   g_offsets[NEXP];
__device__ int   g_token[NSLOT];
__device__ float g_weight[NSLOT];
// hi/lo bf16 planes
__device__ __nv_bfloat16 g_xh[(size_t)NTOK * HID];
__device__ __nv_bfloat16 g_xl[(size_t)NTOK * HID];
__device__ __nv_bfloat16 g_gh[(size_t)NEXP * INTER_ * HID];
__device__ __nv_bfloat16 g_gl[(size_t)NEXP * INTER_ * HID];
__device__ __nv_bfloat16 g_uh[(size_t)NEXP * INTER_ * HID];
__device__ __nv_bfloat16 g_ul[(size_t)NEXP * INTER_ * HID];
__device__ __nv_bfloat16 g_dh[(size_t)NEXP * HID * INTER_];
__device__ __nv_bfloat16 g_dl[(size_t)NEXP * HID * INTER_];
__device__ __nv_bfloat16 g_ih[(size_t)NSLOT * INTER_];
__device__ __nv_bfloat16 g_il[(size_t)NSLOT * INTER_];

// ---------------- helpers ----------------
__device__ __forceinline__ uint32_t smem_u32(const void* p) {
    uint32_t a;
    asm("{ .reg .u64 t; cvta.to.shared.u64 t, %1; cvt.u32.u64 %0, t; }" : "=r"(a) : "l"(p));
    return a;
}
#define CP16(sm, gm) asm volatile("cp.async.cg.shared.global [%0], [%1], 16;" :: "r"(sm), "l"(gm))
#define CP_COMMIT()  asm volatile("cp.async.commit_group;" ::: "memory")
#define CP_WAIT(n)   asm volatile("cp.async.wait_group %0;" :: "n"(n) : "memory")

__device__ __forceinline__ void mma_bf16(float* c, const uint32_t* a, const uint32_t* b) {
    asm volatile(
        "mma.sync.aligned.m16n8k16.row.col.f32.bf16.bf16.f32 "
        "{%0,%1,%2,%3}, {%4,%5,%6,%7}, {%8,%9}, {%0,%1,%2,%3};\n"
        : "+f"(c[0]), "+f"(c[1]), "+f"(c[2]), "+f"(c[3])
        : "r"(a[0]), "r"(a[1]), "r"(a[2]), "r"(a[3]), "r"(b[0]), "r"(b[1]));
}

__device__ __forceinline__ uint32_t packhl(float a, float b, float& ra, float& rb) {
    __nv_bfloat16 ha = __float2bfloat16(a);
    __nv_bfloat16 hb = __float2bfloat16(b);
    ra = a - __bfloat162float(ha);
    rb = b - __bfloat162float(hb);
    __nv_bfloat162 p = __halves2bfloat162(ha, hb);
    return *reinterpret_cast<uint32_t*>(&p);
}
__device__ __forceinline__ uint32_t packlo(float a, float b) {
    __nv_bfloat162 p = __halves2bfloat162(__float2bfloat16(a), __float2bfloat16(b));
    return *reinterpret_cast<uint32_t*>(&p);
}

// ---------------- split: fp32 -> hi/lo bf16 planes ----------------
__global__ void split_kernel(const float4* __restrict__ src,
                             uint2* __restrict__ hi, uint2* __restrict__ lo, int n4) {
    int i = blockIdx.x * blockDim.x + threadIdx.x;
    if (i >= n4) return;
    float4 v = src[i];
    float rx, ry, rz, rw;
    uint2 H, L;
    H.x = packhl(v.x, v.y, rx, ry);
    H.y = packhl(v.z, v.w, rz, rw);
    L.x = packlo(rx, ry);
    L.y = packlo(rz, rw);
    hi[i] = H;
    lo[i] = L;
}

// ---------------- routing ----------------
__global__ void route_kernel(const int* __restrict__ idxw,
                             const float* __restrict__ wts) {
    __shared__ int cnt[NEXP], off[NEXP], cur[NEXP];
    __shared__ int not64;
    int tid = threadIdx.x;
    if (tid < NEXP) { cnt[tid] = 0; cur[tid] = 0; }
    if (tid == 0) not64 = 0;
    __syncthreads();
    int any = 0;
    for (int i = 2 * tid + 1; i < NSLOT; i += 2 * blockDim.x) any |= idxw[i];
    if (any) atomicOr(&not64, 1);
    __syncthreads();
    const int is64 = !not64;
    for (int s = tid; s < NSLOT; s += blockDim.x) {
        int e = is64 ? idxw[2 * s] : idxw[s];
        atomicAdd(&cnt[e], 1);
    }
    __syncthreads();
    if (tid == 0) {
        int acc = 0;
        for (int e = 0; e < NEXP; e++) {
            off[e] = acc; g_offsets[e] = acc; g_counts[e] = cnt[e];
            acc += cnt[e];
        }
    }
    __syncthreads();
    for (int s = tid; s < NSLOT; s += blockDim.x) {
        int e = is64 ? idxw[2 * s] : idxw[s];
        int p = off[e] + atomicAdd(&cur[e], 1);
        g_token[p]  = s >> 1;
        g_weight[p] = wts[s];
    }
}

__global__ void zero_kernel(float4* __restrict__ out, int n4) {
    int i = blockIdx.x * blockDim.x + threadIdx.x;
    if (i < n4) out[i] = make_float4(0.f, 0.f, 0.f, 0.f);
}

// ---------------- GEMM 1: gate+up, 3x-bf16 mma ----------------
// grid (INTER_/64=16, 32, NEXP). C = 128 slots x (64 gate | 64 up) cols.
__global__ __launch_bounds__(256, 2)
void gemm_gu_mma(void) {
    const int e   = blockIdx.z;
    const int cnt = g_counts[e];
    const int m0  = blockIdx.y * 128;
    if (m0 >= cnt) return;
    const int base = g_offsets[e];
    const int n0   = blockIdx.x * 64;

    extern __shared__ char smem[];
    const uint32_t sb = smem_u32(smem);
    int*   sTok = (int*)smem;
    float* sW   = (float*)(smem + 512);

    const int tid  = threadIdx.x;
    const int wid  = tid >> 5;
    const int lane = tid & 31;

    if (tid < 128) {
        int m = m0 + tid;
        int r = base + (m < cnt ? m : cnt - 1);
        sTok[tid] = g_token[r];
        sW[tid]   = (m < cnt) ? g_weight[r] : 0.f;
    }
    __syncthreads();

    const int lrow  = tid >> 1;
    const int lhalf = tid & 1;
    const __nv_bfloat16* aRowH = g_xh + (size_t)sTok[lrow] * HID;
    const __nv_bfloat16* aRowL = g_xl + (size_t)sTok[lrow] * HID;
    const __nv_bfloat16* bRowH = (lrow < 64)
        ? g_gh + ((size_t)e * INTER_ + n0 + lrow) * HID
        : g_uh + ((size_t)e * INTER_ + n0 + lrow - 64) * HID;
    const __nv_bfloat16* bRowL = (lrow < 64)
        ? g_gl + ((size_t)e * INTER_ + n0 + lrow) * HID
        : g_ul + ((size_t)e * INTER_ + n0 + lrow - 64) * HID;
    const uint32_t roff = (uint32_t)(lrow * ROWB + lhalf * 32);

    const int wm = wid >> 2, wn = wid & 3;
    const int g  = lane >> 2, t4 = lane & 3;

    float acc[4][4][4];
    #pragma unroll
    for (int i = 0; i < 4; i++)
        #pragma unroll
        for (int j = 0; j < 4; j++)
            #pragma unroll
            for (int r = 0; r < 4; r++) acc[i][j][r] = 0.f;

    const int NT = HID / KT;   // 64

    // prologue: stage 0
    {
        const int src = lhalf * 16;
        CP16(sb + SM_AH(0) + roff,      aRowH + src);
        CP16(sb + SM_AH(0) + roff + 16, aRowH + src + 8);
        CP16(sb + SM_AL(0) + roff,      aRowL + src);
        CP16(sb + SM_AL(0) + roff + 16, aRowL + src + 8);
        CP16(sb + SM_BH(0) + roff,      bRowH + src);
        CP16(sb + SM_BH(0) + roff + 16, bRowH + src + 8);
        CP16(sb + SM_BL(0) + roff,      bRowL + src);
        CP16(sb + SM_BL(0) + roff + 16, bRowL + src + 8);
        CP_COMMIT();
    }

    for (int t = 0; t < NT; t++) {
        if (t + 1 < NT) {
            const int b = (t + 1) & 1;
            const int src = (t + 1) * KT + lhalf * 16;
            CP16(sb + SM_AH(b) + roff,      aRowH + src);
            CP16(sb + SM_AH(b) + roff + 16, aRowH + src + 8);
            CP16(sb + SM_AL(b) + roff,      aRowL + src);
            CP16(sb + SM_AL(b) + roff + 16, aRowL + src + 8);
            CP16(sb + SM_BH(b) + roff,      bRowH + src);
            CP16(sb + SM_BH(b) + roff + 16, bRowH + src + 8);
            CP16(sb + SM_BL(b) + roff,      bRowL + src);
            CP16(sb + SM_BL(b) + roff + 16, bRowL + src + 8);
            CP_COMMIT();
            CP_WAIT(1);
        } else {
            CP_WAIT(0);
        }
        __syncthreads();

        const int buf = t & 1;
        const uint32_t* AhW = (const uint32_t*)(smem + SM_AH(buf));
        const uint32_t* AlW = (const uint32_t*)(smem + SM_AL(buf));
        const uint32_t* BhW = (const uint32_t*)(smem + SM_BH(buf));
        const uint32_t* BlW = (const uint32_t*)(smem + SM_BL(buf));
        #pragma unroll
        for (int ks = 0; ks < 2; ks++) {
            const int kw = ks * 8 + t4;
            uint32_t ah[4][4], al[4][4];
            #pragma unroll
            for (int mt = 0; mt < 4; mt++) {
                int r0 = (wm * 64 + mt * 16 + g) * ROWW;
                ah[mt][0] = AhW[r0 + kw];
                ah[mt][1] = AhW[r0 + 160 + kw];
                ah[mt][2] = AhW[r0 + kw + 4];
                ah[mt][3] = AhW[r0 + 160 + kw + 4];
                al[mt][0] = AlW[r0 + kw];
                al[mt][1] = AlW[r0 + 160 + kw];
                al[mt][2] = AlW[r0 + kw + 4];
                al[mt][3] = AlW[r0 + 160 + kw + 4];
            }
            uint32_t bh[4][2], bl[4][2];
            #pragma unroll
            for (int nt = 0; nt < 4; nt++) {
                int rn = (wn * 32 + nt * 8 + g) * ROWW;
                bh[nt][0] = BhW[rn + kw];
                bh[nt][1] = BhW[rn + kw + 4];
                bl[nt][0] = BlW[rn + kw];
                bl[nt][1] = BlW[rn + kw + 4];
            }
            #pragma unroll
            for (int mt = 0; mt < 4; mt++)
                #pragma unroll
                for (int nt = 0; nt < 4; nt++) {
                    mma_bf16(acc[mt][nt], al[mt], bh[nt]);
                    mma_bf16(acc[mt][nt], ah[mt], bl[nt]);
                    mma_bf16(acc[mt][nt], ah[mt], bh[nt]);
                }
        }
        __syncthreads();
    }

    // stage accumulators to smem, SwiGLU-combine, split to hi/lo bf16 planes
    float* Cs = (float*)(smem + SM_BUF);
    #pragma unroll
    for (int mt = 0; mt < 4; mt++) {
        #pragma unroll
        for (int nt = 0; nt < 4; nt++) {
            int row = wm * 64 + mt * 16 + g;
            int col = wn * 32 + nt * 8 + t4 * 2;
            *reinterpret_cast<float2*>(&Cs[row * CS_STRIDE + col]) =
                make_float2(acc[mt][nt][0], acc[mt][nt][1]);
            *reinterpret_cast<float2*>(&Cs[(row + 8) * CS_STRIDE + col]) =
                make_float2(acc[mt][nt][2], acc[mt][nt][3]);
        }
    }
    __syncthreads();

    const int jj = (tid & 15) * 4;
    const int rb = (tid >> 4) * 8;
    #pragma unroll
    for (int mm = 0; mm < 8; mm++) {
        int m = rb + mm;
        if (m0 + m >= cnt) continue;
        float w = sW[m];
        float4 gv = *reinterpret_cast<const float4*>(&Cs[m * CS_STRIDE + jj]);
        float4 uv = *reinterpret_cast<const float4*>(&Cs[m * CS_STRIDE + 64 + jj]);
        float o0 = (gv.x / (1.f + __expf(-gv.x))) * uv.x * w;
        float o1 = (gv.y / (1.f + __expf(-gv.y))) * uv.y * w;
        float o2 = (gv.z / (1.f + __expf(-gv.z))) * uv.z * w;
        float o3 = (gv.w / (1.f + __expf(-gv.w))) * uv.w * w;
        float r0, r1, r2, r3;
        uint2 H, L;
        H.x = packhl(o0, o1, r0, r1);
        H.y = packhl(o2, o3, r2, r3);
        L.x = packlo(r0, r1);
        L.y = packlo(r2, r3);
        size_t idx = (size_t)(base + m0 + m) * INTER_ + n0 + jj;
        *reinterpret_cast<uint2*>(&g_ih[idx]) = H;
        *reinterpret_cast<uint2*>(&g_il[idx]) = L;
    }
}

// ---------------- GEMM 2: down, 3x-bf16 mma + scatter ----------------
// grid (HID/128=16, 32, NEXP). C = 128 x 128.
__global__ __launch_bounds__(256, 2)
void gemm_down_mma(float* __restrict__ out) {
    const int e   = blockIdx.z;
    const int cnt = g_counts[e];
    const int m0  = blockIdx.y * 128;
    if (m0 >= cnt) return;
    const int base = g_offsets[e];
    const int n0   = blockIdx.x * 128;

    extern __shared__ char smem[];
    const uint32_t sb = smem_u32(smem);
    int* sTok = (int*)smem;

    const int tid  = threadIdx.x;
    const int wid  = tid >> 5;
    const int lane = tid & 31;

    if (tid < 128) {
        int m = m0 + tid;
        int r = base + (m < cnt ? m : cnt - 1);
        sTok[tid] = g_token[r];
    }
    __syncthreads();

    const int lrow  = tid >> 1;
    const int lhalf = tid & 1;
    int ar = base + m0 + lrow; if (ar > NSLOT - 1) ar = NSLOT - 1;
    const __nv_bfloat16* aRowH = g_ih + (size_t)ar * INTER_;
    const __nv_bfloat16* aRowL = g_il + (size_t)ar * INTER_;
    const __nv_bfloat16* bRowH = g_dh + ((size_t)e * HID + n0 + lrow) * INTER_;
    const __nv_bfloat16* bRowL = g_dl + ((size_t)e * HID + n0 + lrow) * INTER_;
    const uint32_t roff = (uint32_t)(lrow * ROWB + lhalf * 32);

    const int wm = wid >> 2, wn = wid & 3;
    const int g  = lane >> 2, t4 = lane & 3;

    float acc[4][4][4];
    #pragma unroll
    for (int i = 0; i < 4; i++)
        #pragma unroll
        for (int j = 0; j < 4; j++)
            #pragma unroll
            for (int r = 0; r < 4; r++) acc[i][j][r] = 0.f;

    const int NT = INTER_ / KT;   // 32

    {
        const int src = lhalf * 16;
        CP16(sb + SM_AH(0) + roff,      aRowH + src);
        CP16(sb + SM_AH(0) + roff + 16, aRowH + src + 8);
        CP16(sb + SM_AL(0) + roff,      aRowL + src);
        CP16(sb + SM_AL(0) + roff + 16, aRowL + src + 8);
        CP16(sb + SM_BH(0) + roff,      bRowH + src);
        CP16(sb + SM_BH(0) + roff + 16, bRowH + src + 8);
        CP16(sb + SM_BL(0) + roff,      bRowL + src);
        CP16(sb + SM_BL(0) + roff + 16, bRowL + src + 8);
        CP_COMMIT();
    }

    for (int t = 0; t < NT; t++) {
        if (t + 1 < NT) {
            const int b = (t + 1) & 1;
            const int src = (t + 1) * KT + lhalf * 16;
            CP16(sb + SM_AH(b) + roff,      aRowH + src);
            CP16(sb + SM_AH(b) + roff + 16, aRowH + src + 8);
            CP16(sb + SM_AL(b) + roff,      aRowL + src);
            CP16(sb + SM_AL(b) + roff + 16, aRowL + src + 8);
            CP16(sb + SM_BH(b) + roff,      bRowH + src);
            CP16(sb + SM_BH(b) + roff + 16, bRowH + src + 8);
            CP16(sb + SM_BL(b) + roff,      bRowL + src);
            CP16(sb + SM_BL(b) + roff + 16, bRowL + src + 8);
            CP_COMMIT();
            CP_WAIT(1);
        } else {
            CP_WAIT(0);
        }
        __syncthreads();

        const int buf = t & 1;
        const uint32_t* AhW = (const uint32_t*)(smem + SM_AH(buf));
        const uint32_t* AlW = (const uint32_t*)(smem + SM_AL(buf));
        const uint32_t* BhW = (const uint32_t*)(smem + SM_BH(buf));
        const uint32_t* BlW = (const uint32_t*)(smem + SM_BL(buf));
        #pragma unroll
        for (int ks = 0; ks < 2; ks++) {
            const int kw = ks * 8 + t4;
            uint32_t ah[4][4], al[4][4];
            #pragma unroll
            for (int mt = 0; mt < 4; mt++) {
                int r0 = (wm * 64 + mt * 16 + g) * ROWW;
                ah[mt][0] = AhW[r0 + kw];
                ah[mt][1] = AhW[r0 + 160 + kw];
                ah[mt][2] = AhW[r0 + kw + 4];
                ah[mt][3] = AhW[r0 + 160 + kw + 4];
                al[mt][0] = AlW[r0 + kw];
                al[mt][1] = AlW[r0 + 160 + kw];
                al[mt][2] = AlW[r0 + kw + 4];
                al[mt][3] = AlW[r0 + 160 + kw + 4];
            }
            uint32_t bh[4][2], bl[4][2];
            #pragma unroll
            for (int nt = 0; nt < 4; nt++) {
                int rn = (wn * 32 + nt * 8 + g) * ROWW;
                bh[nt][0] = BhW[rn + kw];
                bh[nt][1] = BhW[rn + kw + 4];
                bl[nt][0] = BlW[rn + kw];
                bl[nt][1] = BlW[rn + kw + 4];
            }
            #pragma unroll
            for (int mt = 0; mt < 4; mt++)
                #pragma unroll
                for (int nt = 0; nt < 4; nt++) {
                    mma_bf16(acc[mt][nt], al[mt], bh[nt]);
                    mma_bf16(acc[mt][nt], ah[mt], bl[nt]);
                    mma_bf16(acc[mt][nt], ah[mt], bh[nt]);
                }
        }
        __syncthreads();
    }

    // scatter
    #pragma unroll
    for (int mt = 0; mt < 4; mt++) {
        int row0 = wm * 64 + mt * 16 + g;
        int row1 = row0 + 8;
        bool v0 = (m0 + row0 < cnt);
        bool v1 = (m0 + row1 < cnt);
        float* o0 = out + (size_t)sTok[row0] * HID + n0;
        float* o1 = out + (size_t)sTok[row1] * HID + n0;
        #pragma unroll
        for (int nt = 0; nt < 4; nt++) {
            int col = wn * 32 + nt * 8 + t4 * 2;
            if (v0) {
                atomicAdd(&o0[col],     acc[mt][nt][0]);
                atomicAdd(&o0[col + 1], acc[mt][nt][1]);
            }
            if (v1) {
                atomicAdd(&o1[col],     acc[mt][nt][2]);
                atomicAdd(&o1[col + 1], acc[mt][nt][3]);
            }
        }
    }
}

// ---------------- launch ----------------
extern "C" void kernel_launch(void* const* d_in, const int* in_sizes, int n_in,
                              void* d_out, int out_size) {
    const float* x    = (const float*)d_in[0];
    const int*   idxw = (const int*)d_in[1];
    const float* wts  = (const float*)d_in[2];
    const float* gate = (const float*)d_in[3];
    const float* up   = (const float*)d_in[4];
    const float* down = (const float*)d_in[5];
    float* out = (float*)d_out;

    cudaFuncSetAttribute(gemm_gu_mma,   cudaFuncAttributeMaxDynamicSharedMemorySize, SM_TOTAL);
    cudaFuncSetAttribute(gemm_down_mma, cudaFuncAttributeMaxDynamicSharedMemorySize, SM_TOTAL);

    // resolve device scratch addresses
    __nv_bfloat16 *xh, *xl, *gh, *gl, *uh, *ul, *dh, *dl;
    cudaGetSymbolAddress((void**)&xh, g_xh);
    cudaGetSymbolAddress((void**)&xl, g_xl);
    cudaGetSymbolAddress((void**)&gh, g_gh);
    cudaGetSymbolAddress((void**)&gl, g_gl);
    cudaGetSymbolAddress((void**)&uh, g_uh);
    cudaGetSymbolAddress((void**)&ul, g_ul);
    cudaGetSymbolAddress((void**)&dh, g_dh);
    cudaGetSymbolAddress((void**)&dl, g_dl);

    int n4 = out_size / 4;
    zero_kernel<<<(n4 + 255) / 256, 256>>>((float4*)out, n4);
    route_kernel<<<1, 256>>>(idxw, wts);

    {
        int nx = NTOK * HID / 4;
        split_kernel<<<(nx + 255) / 256, 256>>>((const float4*)x, (uint2*)xh, (uint2*)xl, nx);
        int nw = NEXP * INTER_ * HID / 4;
        split_kernel<<<(nw + 255) / 256, 256>>>((const float4*)gate, (uint2*)gh, (uint2*)gl, nw);
        split_kernel<<<(nw + 255) / 256, 256>>>((const float4*)up,   (uint2*)uh, (uint2*)ul, nw);
        split_kernel<<<(nw + 255) / 256, 256>>>((const float4*)down, (uint2*)dh, (uint2*)dl, nw);
    }
    {
        dim3 grid(INTER_ / 64, NSLOT / 128, NEXP);
        gemm_gu_mma<<<grid, 256, SM_TOTAL>>>();
    }
    {
        dim3 grid(HID / 128, NSLOT / 128, NEXP);
        gemm_down_mma<<<grid, 256, SM_TOTAL>>>(out);
    }
}

// round 7
// speedup vs baseline: 2.6166x; 1.0637x over previous
#include <cuda_runtime.h>
#include <cuda_bf16.h>
#include <math.h>
#include <stdint.h>

// Problem constants
#define NTOK   2048
#define HID    2048
#define INTER_ 1024
#define NEXP   8
#define TOPK   2
#define NSLOT  (NTOK * TOPK)

// MMA tiling: block 128x128 C, 8 warps (2x4), warp 64x32, k-tile 32 (bf16)
#define KT    32
#define ROWB  80          // bytes per padded smem row (64B data + 16B pad)
#define ROWW  20          // 32-bit words per row
#define TILE  10240       // 128 rows * 80B
#define SM_BUF 1024
#define SM_AH(b) (SM_BUF + (b) * 4 * TILE)
#define SM_AL(b) (SM_AH(b) + TILE)
#define SM_BH(b) (SM_AH(b) + 2 * TILE)
#define SM_BL(b) (SM_AH(b) + 3 * TILE)
#define SM_TOTAL (SM_BUF + 8 * TILE)     // 82944
#define CS_STRIDE 132

// -------- device scratch --------
__device__ int   g_counts[NEXP];
__device__ int   g_offsets[NEXP];
__device__ int   g_token[NSLOT];
__device__ float g_weight[NSLOT];
// hi/lo bf16 planes
__device__ __nv_bfloat16 g_xh[(size_t)NTOK * HID];
__device__ __nv_bfloat16 g_xl[(size_t)NTOK * HID];
__device__ __nv_bfloat16 g_gh[(size_t)NEXP * INTER_ * HID];
__device__ __nv_bfloat16 g_gl[(size_t)NEXP * INTER_ * HID];
__device__ __nv_bfloat16 g_uh[(size_t)NEXP * INTER_ * HID];
__device__ __nv_bfloat16 g_ul[(size_t)NEXP * INTER_ * HID];
__device__ __nv_bfloat16 g_dh[(size_t)NEXP * HID * INTER_];
__device__ __nv_bfloat16 g_dl[(size_t)NEXP * HID * INTER_];
__device__ __nv_bfloat16 g_ih[(size_t)NSLOT * INTER_];
__device__ __nv_bfloat16 g_il[(size_t)NSLOT * INTER_];

// ---------------- helpers ----------------
__device__ __forceinline__ uint32_t smem_u32(const void* p) {
    uint32_t a;
    asm("{ .reg .u64 t; cvta.to.shared.u64 t, %1; cvt.u32.u64 %0, t; }" : "=r"(a) : "l"(p));
    return a;
}
#define CP16(sm, gm) asm volatile("cp.async.cg.shared.global [%0], [%1], 16;" :: "r"(sm), "l"(gm))
#define CP_COMMIT()  asm volatile("cp.async.commit_group;" ::: "memory")
#define CP_WAIT(n)   asm volatile("cp.async.wait_group %0;" :: "n"(n) : "memory")

__device__ __forceinline__ void mma_bf16(float* c, const uint32_t* a, const uint32_t* b) {
    asm volatile(
        "mma.sync.aligned.m16n8k16.row.col.f32.bf16.bf16.f32 "
        "{%0,%1,%2,%3}, {%4,%5,%6,%7}, {%8,%9}, {%0,%1,%2,%3};\n"
        : "+f"(c[0]), "+f"(c[1]), "+f"(c[2]), "+f"(c[3])
        : "r"(a[0]), "r"(a[1]), "r"(a[2]), "r"(a[3]), "r"(b[0]), "r"(b[1]));
}
__device__ __forceinline__ void ldm_x4(uint32_t* r, uint32_t addr) {
    asm volatile("ldmatrix.sync.aligned.m8n8.x4.shared.b16 {%0,%1,%2,%3}, [%4];"
        : "=r"(r[0]), "=r"(r[1]), "=r"(r[2]), "=r"(r[3]) : "r"(addr));
}

__device__ __forceinline__ uint32_t packhl(float a, float b, float& ra, float& rb) {
    __nv_bfloat16 ha = __float2bfloat16(a);
    __nv_bfloat16 hb = __float2bfloat16(b);
    ra = a - __bfloat162float(ha);
    rb = b - __bfloat162float(hb);
    __nv_bfloat162 p = __halves2bfloat162(ha, hb);
    return *reinterpret_cast<uint32_t*>(&p);
}
__device__ __forceinline__ uint32_t packlo(float a, float b) {
    __nv_bfloat162 p = __halves2bfloat162(__float2bfloat16(a), __float2bfloat16(b));
    return *reinterpret_cast<uint32_t*>(&p);
}

// ---------------- split: fp32 -> hi/lo bf16 planes ----------------
__global__ void split_kernel(const float4* __restrict__ src,
                             uint2* __restrict__ hi, uint2* __restrict__ lo, int n4) {
    int i = blockIdx.x * blockDim.x + threadIdx.x;
    if (i >= n4) return;
    float4 v = src[i];
    float rx, ry, rz, rw;
    uint2 H, L;
    H.x = packhl(v.x, v.y, rx, ry);
    H.y = packhl(v.z, v.w, rz, rw);
    L.x = packlo(rx, ry);
    L.y = packlo(rz, rw);
    hi[i] = H;
    lo[i] = L;
}

// ---------------- routing ----------------
__global__ void route_kernel(const int* __restrict__ idxw,
                             const float* __restrict__ wts) {
    __shared__ int cnt[NEXP], off[NEXP], cur[NEXP];
    __shared__ int not64;
    int tid = threadIdx.x;
    if (tid < NEXP) { cnt[tid] = 0; cur[tid] = 0; }
    if (tid == 0) not64 = 0;
    __syncthreads();
    int any = 0;
    for (int i = 2 * tid + 1; i < NSLOT; i += 2 * blockDim.x) any |= idxw[i];
    if (any) atomicOr(&not64, 1);
    __syncthreads();
    const int is64 = !not64;
    for (int s = tid; s < NSLOT; s += blockDim.x) {
        int e = is64 ? idxw[2 * s] : idxw[s];
        atomicAdd(&cnt[e], 1);
    }
    __syncthreads();
    if (tid == 0) {
        int acc = 0;
        for (int e = 0; e < NEXP; e++) {
            off[e] = acc; g_offsets[e] = acc; g_counts[e] = cnt[e];
            acc += cnt[e];
        }
    }
    __syncthreads();
    for (int s = tid; s < NSLOT; s += blockDim.x) {
        int e = is64 ? idxw[2 * s] : idxw[s];
        int p = off[e] + atomicAdd(&cur[e], 1);
        g_token[p]  = s >> 1;
        g_weight[p] = wts[s];
    }
}

__global__ void zero_kernel(float4* __restrict__ out, int n4) {
    int i = blockIdx.x * blockDim.x + threadIdx.x;
    if (i < n4) out[i] = make_float4(0.f, 0.f, 0.f, 0.f);
}

// ---------------- GEMM 1: gate+up, 3x-bf16 mma, ldmatrix fragments --------
// grid (INTER_/64=16, 32, NEXP). C = 128 slots x (64 gate | 64 up) cols.
__global__ __launch_bounds__(256, 2)
void gemm_gu_mma(void) {
    const int e   = blockIdx.z;
    const int cnt = g_counts[e];
    const int m0  = blockIdx.y * 128;
    if (m0 >= cnt) return;
    const int base = g_offsets[e];
    const int n0   = blockIdx.x * 64;

    extern __shared__ char smem[];
    const uint32_t sb = smem_u32(smem);
    int*   sTok = (int*)smem;
    float* sW   = (float*)(smem + 512);

    const int tid  = threadIdx.x;
    const int wid  = tid >> 5;
    const int lane = tid & 31;

    if (tid < 128) {
        int m = m0 + tid;
        int r = base + (m < cnt ? m : cnt - 1);
        sTok[tid] = g_token[r];
        sW[tid]   = (m < cnt) ? g_weight[r] : 0.f;
    }
    __syncthreads();

    const int lrow  = tid >> 1;
    const int lhalf = tid & 1;
    const __nv_bfloat16* aRowH = g_xh + (size_t)sTok[lrow] * HID;
    const __nv_bfloat16* aRowL = g_xl + (size_t)sTok[lrow] * HID;
    const __nv_bfloat16* bRowH = (lrow < 64)
        ? g_gh + ((size_t)e * INTER_ + n0 + lrow) * HID
        : g_uh + ((size_t)e * INTER_ + n0 + lrow - 64) * HID;
    const __nv_bfloat16* bRowL = (lrow < 64)
        ? g_gl + ((size_t)e * INTER_ + n0 + lrow) * HID
        : g_ul + ((size_t)e * INTER_ + n0 + lrow - 64) * HID;
    const uint32_t roff = (uint32_t)(lrow * ROWB + lhalf * 32);

    const int wm = wid >> 2, wn = wid & 3;
    const int g  = lane >> 2, t4 = lane & 3;

    // ldmatrix per-lane byte offsets (within a plane tile)
    const int lg = lane >> 3;      // tile group 0..3
    const int lr7 = lane & 7;      // row within tile
    uint32_t aoff[4], boff[2];
    #pragma unroll
    for (int mt = 0; mt < 4; mt++)
        aoff[mt] = (uint32_t)((wm * 64 + mt * 16 + (lg & 1) * 8 + lr7) * ROWB + (lg >> 1) * 16);
    #pragma unroll
    for (int p = 0; p < 2; p++)
        boff[p] = (uint32_t)((wn * 32 + (2 * p + (lg >> 1)) * 8 + lr7) * ROWB + (lg & 1) * 16);

    float acc[4][4][4];
    #pragma unroll
    for (int i = 0; i < 4; i++)
        #pragma unroll
        for (int j = 0; j < 4; j++)
            #pragma unroll
            for (int r = 0; r < 4; r++) acc[i][j][r] = 0.f;

    const int NT = HID / KT;   // 64

    {
        const int src = lhalf * 16;
        CP16(sb + SM_AH(0) + roff,      aRowH + src);
        CP16(sb + SM_AH(0) + roff + 16, aRowH + src + 8);
        CP16(sb + SM_AL(0) + roff,      aRowL + src);
        CP16(sb + SM_AL(0) + roff + 16, aRowL + src + 8);
        CP16(sb + SM_BH(0) + roff,      bRowH + src);
        CP16(sb + SM_BH(0) + roff + 16, bRowH + src + 8);
        CP16(sb + SM_BL(0) + roff,      bRowL + src);
        CP16(sb + SM_BL(0) + roff + 16, bRowL + src + 8);
        CP_COMMIT();
    }

    for (int t = 0; t < NT; t++) {
        if (t + 1 < NT) {
            const int b = (t + 1) & 1;
            const int src = (t + 1) * KT + lhalf * 16;
            CP16(sb + SM_AH(b) + roff,      aRowH + src);
            CP16(sb + SM_AH(b) + roff + 16, aRowH + src + 8);
            CP16(sb + SM_AL(b) + roff,      aRowL + src);
            CP16(sb + SM_AL(b) + roff + 16, aRowL + src + 8);
            CP16(sb + SM_BH(b) + roff,      bRowH + src);
            CP16(sb + SM_BH(b) + roff + 16, bRowH + src + 8);
            CP16(sb + SM_BL(b) + roff,      bRowL + src);
            CP16(sb + SM_BL(b) + roff + 16, bRowL + src + 8);
            CP_COMMIT();
            CP_WAIT(1);
        } else {
            CP_WAIT(0);
        }
        __syncthreads();

        const int buf = t & 1;
        const uint32_t ahb = sb + SM_AH(buf);
        const uint32_t alb = sb + SM_AL(buf);
        const uint32_t bhb = sb + SM_BH(buf);
        const uint32_t blb = sb + SM_BL(buf);
        #pragma unroll
        for (int ks = 0; ks < 2; ks++) {
            const uint32_t ko = ks * 32;
            uint32_t bh[2][4], bl[2][4];
            ldm_x4(bh[0], bhb + boff[0] + ko);
            ldm_x4(bh[1], bhb + boff[1] + ko);
            ldm_x4(bl[0], blb + boff[0] + ko);
            ldm_x4(bl[1], blb + boff[1] + ko);
            #pragma unroll
            for (int mt = 0; mt < 4; mt++) {
                uint32_t ah[4], al[4];
                ldm_x4(ah, ahb + aoff[mt] + ko);
                ldm_x4(al, alb + aoff[mt] + ko);
                #pragma unroll
                for (int nt = 0; nt < 4; nt++) {
                    const uint32_t* BH = &bh[nt >> 1][(nt & 1) * 2];
                    const uint32_t* BL = &bl[nt >> 1][(nt & 1) * 2];
                    mma_bf16(acc[mt][nt], al, BH);
                    mma_bf16(acc[mt][nt], ah, BL);
                    mma_bf16(acc[mt][nt], ah, BH);
                }
            }
        }
        __syncthreads();
    }

    // stage accumulators to smem, SwiGLU-combine, split to hi/lo planes
    float* Cs = (float*)(smem + SM_BUF);
    #pragma unroll
    for (int mt = 0; mt < 4; mt++) {
        #pragma unroll
        for (int nt = 0; nt < 4; nt++) {
            int row = wm * 64 + mt * 16 + g;
            int col = wn * 32 + nt * 8 + t4 * 2;
            *reinterpret_cast<float2*>(&Cs[row * CS_STRIDE + col]) =
                make_float2(acc[mt][nt][0], acc[mt][nt][1]);
            *reinterpret_cast<float2*>(&Cs[(row + 8) * CS_STRIDE + col]) =
                make_float2(acc[mt][nt][2], acc[mt][nt][3]);
        }
    }
    __syncthreads();

    const int jj = (tid & 15) * 4;
    const int rb = (tid >> 4) * 8;
    #pragma unroll
    for (int mm = 0; mm < 8; mm++) {
        int m = rb + mm;
        if (m0 + m >= cnt) continue;
        float w = sW[m];
        float4 gv = *reinterpret_cast<const float4*>(&Cs[m * CS_STRIDE + jj]);
        float4 uv = *reinterpret_cast<const float4*>(&Cs[m * CS_STRIDE + 64 + jj]);
        float o0 = (gv.x / (1.f + __expf(-gv.x))) * uv.x * w;
        float o1 = (gv.y / (1.f + __expf(-gv.y))) * uv.y * w;
        float o2 = (gv.z / (1.f + __expf(-gv.z))) * uv.z * w;
        float o3 = (gv.w / (1.f + __expf(-gv.w))) * uv.w * w;
        float r0, r1, r2, r3;
        uint2 H, L;
        H.x = packhl(o0, o1, r0, r1);
        H.y = packhl(o2, o3, r2, r3);
        L.x = packlo(r0, r1);
        L.y = packlo(r2, r3);
        size_t idx = (size_t)(base + m0 + m) * INTER_ + n0 + jj;
        *reinterpret_cast<uint2*>(&g_ih[idx]) = H;
        *reinterpret_cast<uint2*>(&g_il[idx]) = L;
    }
}

// ---------------- GEMM 2: down, 3x-bf16 mma, ldmatrix + scatter -----------
// grid (HID/128=16, 32, NEXP). C = 128 x 128.
__global__ __launch_bounds__(256, 2)
void gemm_down_mma(float* __restrict__ out) {
    const int e   = blockIdx.z;
    const int cnt = g_counts[e];
    const int m0  = blockIdx.y * 128;
    if (m0 >= cnt) return;
    const int base = g_offsets[e];
    const int n0   = blockIdx.x * 128;

    extern __shared__ char smem[];
    const uint32_t sb = smem_u32(smem);
    int* sTok = (int*)smem;

    const int tid  = threadIdx.x;
    const int wid  = tid >> 5;
    const int lane = tid & 31;

    if (tid < 128) {
        int m = m0 + tid;
        int r = base + (m < cnt ? m : cnt - 1);
        sTok[tid] = g_token[r];
    }
    __syncthreads();

    const int lrow  = tid >> 1;
    const int lhalf = tid & 1;
    int ar = base + m0 + lrow; if (ar > NSLOT - 1) ar = NSLOT - 1;
    const __nv_bfloat16* aRowH = g_ih + (size_t)ar * INTER_;
    const __nv_bfloat16* aRowL = g_il + (size_t)ar * INTER_;
    const __nv_bfloat16* bRowH = g_dh + ((size_t)e * HID + n0 + lrow) * INTER_;
    const __nv_bfloat16* bRowL = g_dl + ((size_t)e * HID + n0 + lrow) * INTER_;
    const uint32_t roff = (uint32_t)(lrow * ROWB + lhalf * 32);

    const int wm = wid >> 2, wn = wid & 3;
    const int g  = lane >> 2, t4 = lane & 3;

    const int lg = lane >> 3;
    const int lr7 = lane & 7;
    uint32_t aoff[4], boff[2];
    #pragma unroll
    for (int mt = 0; mt < 4; mt++)
        aoff[mt] = (uint32_t)((wm * 64 + mt * 16 + (lg & 1) * 8 + lr7) * ROWB + (lg >> 1) * 16);
    #pragma unroll
    for (int p = 0; p < 2; p++)
        boff[p] = (uint32_t)((wn * 32 + (2 * p + (lg >> 1)) * 8 + lr7) * ROWB + (lg & 1) * 16);

    float acc[4][4][4];
    #pragma unroll
    for (int i = 0; i < 4; i++)
        #pragma unroll
        for (int j = 0; j < 4; j++)
            #pragma unroll
            for (int r = 0; r < 4; r++) acc[i][j][r] = 0.f;

    const int NT = INTER_ / KT;   // 32

    {
        const int src = lhalf * 16;
        CP16(sb + SM_AH(0) + roff,      aRowH + src);
        CP16(sb + SM_AH(0) + roff + 16, aRowH + src + 8);
        CP16(sb + SM_AL(0) + roff,      aRowL + src);
        CP16(sb + SM_AL(0) + roff + 16, aRowL + src + 8);
        CP16(sb + SM_BH(0) + roff,      bRowH + src);
        CP16(sb + SM_BH(0) + roff + 16, bRowH + src + 8);
        CP16(sb + SM_BL(0) + roff,      bRowL + src);
        CP16(sb + SM_BL(0) + roff + 16, bRowL + src + 8);
        CP_COMMIT();
    }

    for (int t = 0; t < NT; t++) {
        if (t + 1 < NT) {
            const int b = (t + 1) & 1;
            const int src = (t + 1) * KT + lhalf * 16;
            CP16(sb + SM_AH(b) + roff,      aRowH + src);
            CP16(sb + SM_AH(b) + roff + 16, aRowH + src + 8);
            CP16(sb + SM_AL(b) + roff,      aRowL + src);
            CP16(sb + SM_AL(b) + roff + 16, aRowL + src + 8);
            CP16(sb + SM_BH(b) + roff,      bRowH + src);
            CP16(sb + SM_BH(b) + roff + 16, bRowH + src + 8);
            CP16(sb + SM_BL(b) + roff,      bRowL + src);
            CP16(sb + SM_BL(b) + roff + 16, bRowL + src + 8);
            CP_COMMIT();
            CP_WAIT(1);
        } else {
            CP_WAIT(0);
        }
        __syncthreads();

        const int buf = t & 1;
        const uint32_t ahb = sb + SM_AH(buf);
        const uint32_t alb = sb + SM_AL(buf);
        const uint32_t bhb = sb + SM_BH(buf);
        const uint32_t blb = sb + SM_BL(buf);
        #pragma unroll
        for (int ks = 0; ks < 2; ks++) {
            const uint32_t ko = ks * 32;
            uint32_t bh[2][4], bl[2][4];
            ldm_x4(bh[0], bhb + boff[0] + ko);
            ldm_x4(bh[1], bhb + boff[1] + ko);
            ldm_x4(bl[0], blb + boff[0] + ko);
            ldm_x4(bl[1], blb + boff[1] + ko);
            #pragma unroll
            for (int mt = 0; mt < 4; mt++) {
                uint32_t ah[4], al[4];
                ldm_x4(ah, ahb + aoff[mt] + ko);
                ldm_x4(al, alb + aoff[mt] + ko);
                #pragma unroll
                for (int nt = 0; nt < 4; nt++) {
                    const uint32_t* BH = &bh[nt >> 1][(nt & 1) * 2];
                    const uint32_t* BL = &bl[nt >> 1][(nt & 1) * 2];
                    mma_bf16(acc[mt][nt], al, BH);
                    mma_bf16(acc[mt][nt], ah, BL);
                    mma_bf16(acc[mt][nt], ah, BH);
                }
            }
        }
        __syncthreads();
    }

    // scatter
    #pragma unroll
    for (int mt = 0; mt < 4; mt++) {
        int row0 = wm * 64 + mt * 16 + g;
        int row1 = row0 + 8;
        bool v0 = (m0 + row0 < cnt);
        bool v1 = (m0 + row1 < cnt);
        float* o0 = out + (size_t)sTok[row0] * HID + n0;
        float* o1 = out + (size_t)sTok[row1] * HID + n0;
        #pragma unroll
        for (int nt = 0; nt < 4; nt++) {
            int col = wn * 32 + nt * 8 + t4 * 2;
            if (v0) {
                atomicAdd(&o0[col],     acc[mt][nt][0]);
                atomicAdd(&o0[col + 1], acc[mt][nt][1]);
            }
            if (v1) {
                atomicAdd(&o1[col],     acc[mt][nt][2]);
                atomicAdd(&o1[col + 1], acc[mt][nt][3]);
            }
        }
    }
}

// ---------------- launch ----------------
extern "C" void kernel_launch(void* const* d_in, const int* in_sizes, int n_in,
                              void* d_out, int out_size) {
    const float* x    = (const float*)d_in[0];
    const int*   idxw = (const int*)d_in[1];
    const float* wts  = (const float*)d_in[2];
    const float* gate = (const float*)d_in[3];
    const float* up   = (const float*)d_in[4];
    const float* down = (const float*)d_in[5];
    float* out = (float*)d_out;

    cudaFuncSetAttribute(gemm_gu_mma,   cudaFuncAttributeMaxDynamicSharedMemorySize, SM_TOTAL);
    cudaFuncSetAttribute(gemm_down_mma, cudaFuncAttributeMaxDynamicSharedMemorySize, SM_TOTAL);

    __nv_bfloat16 *xh, *xl, *gh, *gl, *uh, *ul, *dh, *dl;
    cudaGetSymbolAddress((void**)&xh, g_xh);
    cudaGetSymbolAddress((void**)&xl, g_xl);
    cudaGetSymbolAddress((void**)&gh, g_gh);
    cudaGetSymbolAddress((void**)&gl, g_gl);
    cudaGetSymbolAddress((void**)&uh, g_uh);
    cudaGetSymbolAddress((void**)&ul, g_ul);
    cudaGetSymbolAddress((void**)&dh, g_dh);
    cudaGetSymbolAddress((void**)&dl, g_dl);

    int n4 = out_size / 4;
    zero_kernel<<<(n4 + 255) / 256, 256>>>((float4*)out, n4);
    route_kernel<<<1, 256>>>(idxw, wts);

    {
        int nx = NTOK * HID / 4;
        split_kernel<<<(nx + 255) / 256, 256>>>((const float4*)x, (uint2*)xh, (uint2*)xl, nx);
        int nw = NEXP * INTER_ * HID / 4;
        split_kernel<<<(nw + 255) / 256, 256>>>((const float4*)gate, (uint2*)gh, (uint2*)gl, nw);
        split_kernel<<<(nw + 255) / 256, 256>>>((const float4*)up,   (uint2*)uh, (uint2*)ul, nw);
        split_kernel<<<(nw + 255) / 256, 256>>>((const float4*)down, (uint2*)dh, (uint2*)dl, nw);
    }
    {
        dim3 grid(INTER_ / 64, NSLOT / 128, NEXP);
        gemm_gu_mma<<<grid, 256, SM_TOTAL>>>();
    }
    {
        dim3 grid(HID / 128, NSLOT / 128, NEXP);
        gemm_down_mma<<<grid, 256, SM_TOTAL>>>(out);
    }
}